// round 10
// baseline (speedup 1.0000x reference)
#include <cuda_runtime.h>
#include <cuda_bf16.h>
#include <math.h>

#define NN 2048
#define DD 256

// ---------------- scratch (device globals; no allocation) ----------------
__device__ float g_msg[NN * 512];       // [msg0 | msg1] by column halves
__device__ float g_e0[NN * NN];
__device__ float g_e1[NN * NN];
__device__ float g_gi[NN * 768];
__device__ float g_gh[NN * 768];
__device__ float g_ac0[NN * 4];
__device__ float g_an0[NN * 4];
__device__ float g_ac1[NN * 4];
__device__ float g_an1[NN * 4];
__device__ float g_bm[512];             // [bm0 | bm1]

// bf16 split operands
__device__ __nv_bfloat16 g_xhi[NN * 256],  g_xlo[NN * 256];
__device__ __nv_bfloat16 g_ahi[NN * 512],  g_alo[NN * 512];      // agg in bf16 hi/lo
__device__ __nv_bfloat16 g_wmhi[512 * 256], g_wmlo[512 * 256];   // [Wm0 ; Wm1]
__device__ __nv_bfloat16 g_wihhi[768 * 512], g_wihlo[768 * 512];
__device__ __nv_bfloat16 g_whhhi[768 * 256], g_whhlo[768 * 256];

// ---------------- split helper ----------------
__device__ __forceinline__ void do_split(int blk, const float* __restrict__ src,
                                         __nv_bfloat16* __restrict__ hi,
                                         __nv_bfloat16* __restrict__ lo, int n4) {
    int i = blk * 256 + threadIdx.x;
    if (i >= n4) return;
    float4 v = ((const float4*)src)[i];
    float vv[4] = {v.x, v.y, v.z, v.w};
    __nv_bfloat16 h[4], l[4];
    #pragma unroll
    for (int k = 0; k < 4; k++) {
        h[k] = __float2bfloat16(vv[k]);
        l[k] = __float2bfloat16(vv[k] - __bfloat162float(h[k]));
    }
    *(uint2*)&hi[i * 4] = *(uint2*)h;
    *(uint2*)&lo[i * 4] = *(uint2*)l;
}

// ---------------- phase1 mega-kernel ----------------
#define P1_T    8192
#define P1_AC   (P1_T + 2048)
#define P1_SPX  (P1_AC)
#define P1_SPW0 (P1_SPX + 512)
#define P1_SPW1 (P1_SPW0 + 64)
#define P1_SPIH (P1_SPW1 + 64)
#define P1_SPHH (P1_SPIH + 384)
#define P1_BM   (P1_SPHH + 192)
#define P1_GRID (P1_BM + 1)

__global__ void phase1(const float* __restrict__ x,
                       const float* __restrict__ adj0, const float* __restrict__ w0,
                       const float* __restrict__ adj1, const float* __restrict__ w1,
                       const float* __restrict__ Wa0, const float* __restrict__ Wa1,
                       const float* __restrict__ Wm0, const float* __restrict__ Wm1,
                       const float* __restrict__ wih, const float* __restrict__ whh,
                       const float* __restrict__ bm0, const float* __restrict__ bm1,
                       float* __restrict__ e0, float* __restrict__ e1,
                       float* __restrict__ ac0, float* __restrict__ an0,
                       float* __restrict__ ac1, float* __restrict__ an1,
                       __nv_bfloat16* __restrict__ xhi, __nv_bfloat16* __restrict__ xlo,
                       __nv_bfloat16* __restrict__ wmhi, __nv_bfloat16* __restrict__ wmlo,
                       __nv_bfloat16* __restrict__ wihhi, __nv_bfloat16* __restrict__ wihlo,
                       __nv_bfloat16* __restrict__ whhhi, __nv_bfloat16* __restrict__ whhlo,
                       float* __restrict__ bm) {
    int b = blockIdx.x;
    int tid = threadIdx.x;

    if (b < P1_T) {
        int t = b >> 12;
        int rem = b & 4095;
        int i0 = (rem & 63) * 32, j0 = (rem >> 6) * 32;
        const float* adj = t ? adj1 : adj0;
        const float* w   = t ? w1   : w0;
        float*       e   = t ? e1   : e0;
        __shared__ float tile[32][33];
        int tx = tid & 31, ty = tid >> 5;
        #pragma unroll
        for (int r = 0; r < 4; r++) {
            int j = j0 + ty + r * 8;
            int idx = j * NN + i0 + tx;
            float a = adj[idx];
            tile[ty + r * 8][tx] = (a != 0.f) ? w[idx] : -1.0f;
        }
        __syncthreads();
        #pragma unroll
        for (int r = 0; r < 4; r++) {
            int i = i0 + ty + r * 8;
            e[i * NN + j0 + tx] = tile[tx][ty + r * 8];
        }
        return;
    }
    if (b < P1_AC) {
        int i = b - P1_T;
        __shared__ float xs[256];
        xs[tid] = x[i * 256 + tid];
        __syncthreads();
        int lane = tid & 31, wid = tid >> 5;
        #pragma unroll
        for (int oo = 0; oo < 2; oo++) {
            int o = wid + oo * 8;
            int t = o >> 3, rem = o & 7;
            int half = rem >> 2, h = rem & 3;
            const float* Wa = t ? Wa1 : Wa0;
            const float* row = Wa + h * 512 + half * 256;
            float s = 0.f;
            #pragma unroll
            for (int k = lane; k < 256; k += 32) s += xs[k] * row[k];
            #pragma unroll
            for (int off = 16; off > 0; off >>= 1) s += __shfl_down_sync(0xffffffffu, s, off);
            if (lane == 0) {
                float* dst = half ? (t ? an1 : an0) : (t ? ac1 : ac0);
                dst[i * 4 + h] = s;
            }
        }
        return;
    }
    if (b < P1_SPW0) { do_split(b - P1_SPX,  x,   xhi,   xlo,   NN * 256 / 4); return; }
    if (b < P1_SPW1) { do_split(b - P1_SPW0, Wm0, wmhi,  wmlo,  256 * 256 / 4); return; }
    if (b < P1_SPIH) { do_split(b - P1_SPW1, Wm1, wmhi + 256 * 256, wmlo + 256 * 256, 256 * 256 / 4); return; }
    if (b < P1_SPHH) { do_split(b - P1_SPIH, wih, wihhi, wihlo, 768 * 512 / 4); return; }
    if (b < P1_BM)   { do_split(b - P1_SPHH, whh, whhhi, whhlo, 768 * 256 / 4); return; }
    bm[tid] = bm0[tid];
    bm[tid + 256] = bm1[tid];
}

// ---------------- mma / ldmatrix helpers ----------------
__device__ __forceinline__ void mma16816(float* c, const unsigned* a, const unsigned* b) {
    asm volatile(
        "mma.sync.aligned.m16n8k16.row.col.f32.bf16.bf16.f32 "
        "{%0,%1,%2,%3},{%4,%5,%6,%7},{%8,%9},{%0,%1,%2,%3};"
        : "+f"(c[0]), "+f"(c[1]), "+f"(c[2]), "+f"(c[3])
        : "r"(a[0]), "r"(a[1]), "r"(a[2]), "r"(a[3]), "r"(b[0]), "r"(b[1]));
}

__device__ __forceinline__ void ldsm4(unsigned& r0, unsigned& r1, unsigned& r2, unsigned& r3,
                                      unsigned addr) {
    asm volatile("ldmatrix.sync.aligned.m8n8.x4.shared.b16 {%0,%1,%2,%3},[%4];"
                 : "=r"(r0), "=r"(r1), "=r"(r2), "=r"(r3) : "r"(addr));
}

// ---------------- tensor-core GEMM body (cp.async double-buffered, ldmatrix frags) ----
#define AST 40
#define ASZ (128 * AST)
#define BSZ (64 * AST)
#define GEMM_SMEM ((4 * ASZ + 4 * BSZ) * 2)

__device__ __forceinline__ void gemm_body(
    __nv_bfloat16* smem,
    const __nv_bfloat16* __restrict__ Ahi, const __nv_bfloat16* __restrict__ Alo,
    const __nv_bfloat16* __restrict__ Bhi, const __nv_bfloat16* __restrict__ Blo,
    const float* __restrict__ bias, float* __restrict__ C,
    int Nc, int K, int m0, int n0) {
    __nv_bfloat16* sA = smem;
    __nv_bfloat16* sB = smem + 4 * ASZ;

    int tid = threadIdx.x, lane = tid & 31, wid = tid >> 5;
    int wr = wid >> 1, wc = wid & 1;
    int g = lane >> 2, tq = lane & 3;

    float acc[2][4][4] = {};

    auto issue = [&](int kk, int st) {
        #pragma unroll
        for (int it = 0; it < 2; it++) {
            int ch = tid + it * 256;
            int r = ch >> 2, c = (ch & 3) * 8;
            unsigned dh = (unsigned)__cvta_generic_to_shared(&sA[(st * 2 + 0) * ASZ + r * AST + c]);
            unsigned dl = (unsigned)__cvta_generic_to_shared(&sA[(st * 2 + 1) * ASZ + r * AST + c]);
            asm volatile("cp.async.cg.shared.global [%0],[%1],16;" :: "r"(dh), "l"(&Ahi[(m0 + r) * K + kk + c]));
            asm volatile("cp.async.cg.shared.global [%0],[%1],16;" :: "r"(dl), "l"(&Alo[(m0 + r) * K + kk + c]));
        }
        {
            int r = tid >> 2, c = (tid & 3) * 8;
            unsigned dh = (unsigned)__cvta_generic_to_shared(&sB[(st * 2 + 0) * BSZ + r * AST + c]);
            unsigned dl = (unsigned)__cvta_generic_to_shared(&sB[(st * 2 + 1) * BSZ + r * AST + c]);
            asm volatile("cp.async.cg.shared.global [%0],[%1],16;" :: "r"(dh), "l"(&Bhi[(n0 + r) * K + kk + c]));
            asm volatile("cp.async.cg.shared.global [%0],[%1],16;" :: "r"(dl), "l"(&Blo[(n0 + r) * K + kk + c]));
        }
    };

    // ldmatrix lane addressing (constant across iterations)
    int arow = lane & 15;
    int acol = (lane >> 4) << 3;
    int ti = lane >> 3;
    int brq = ((ti >> 1) << 3) + (lane & 7);
    int bco = (ti & 1) << 3;

    auto compute = [&](int st) {
        unsigned bAh = (unsigned)__cvta_generic_to_shared(sA + (st * 2 + 0) * ASZ);
        unsigned bAl = bAh + ASZ * 2;
        unsigned bBh = (unsigned)__cvta_generic_to_shared(sB + (st * 2 + 0) * BSZ);
        unsigned bBl = bBh + BSZ * 2;
        #pragma unroll
        for (int k16 = 0; k16 < 32; k16 += 16) {
            unsigned ahi[2][4], alo[2][4], bhi[4][2], blo[4][2];
            #pragma unroll
            for (int mt = 0; mt < 2; mt++) {
                unsigned off = ((wr * 32 + mt * 16 + arow) * AST + k16 + acol) * 2;
                ldsm4(ahi[mt][0], ahi[mt][1], ahi[mt][2], ahi[mt][3], bAh + off);
                ldsm4(alo[mt][0], alo[mt][1], alo[mt][2], alo[mt][3], bAl + off);
            }
            #pragma unroll
            for (int p = 0; p < 2; p++) {
                unsigned off = ((wc * 32 + p * 16 + brq) * AST + k16 + bco) * 2;
                ldsm4(bhi[2 * p][0], bhi[2 * p][1], bhi[2 * p + 1][0], bhi[2 * p + 1][1], bBh + off);
                ldsm4(blo[2 * p][0], blo[2 * p][1], blo[2 * p + 1][0], blo[2 * p + 1][1], bBl + off);
            }
            #pragma unroll
            for (int mt = 0; mt < 2; mt++)
                #pragma unroll
                for (int nt = 0; nt < 4; nt++) {
                    mma16816(acc[mt][nt], ahi[mt], bhi[nt]);
                    mma16816(acc[mt][nt], ahi[mt], blo[nt]);
                    mma16816(acc[mt][nt], alo[mt], bhi[nt]);
                }
        }
    };

    int nk = K / 32;
    issue(0, 0);
    asm volatile("cp.async.commit_group;");
    for (int kt = 0; kt < nk; kt++) {
        if (kt + 1 < nk) {
            issue((kt + 1) * 32, (kt + 1) & 1);
            asm volatile("cp.async.commit_group;");
            asm volatile("cp.async.wait_group 1;");
        } else {
            asm volatile("cp.async.wait_group 0;");
        }
        __syncthreads();
        compute(kt & 1);
        __syncthreads();
    }

    #pragma unroll
    for (int mt = 0; mt < 2; mt++) {
        int r0 = m0 + wr * 32 + mt * 16 + g;
        #pragma unroll
        for (int nt = 0; nt < 4; nt++) {
            int c0 = n0 + wc * 32 + nt * 8 + tq * 2;
            float2 b2 = *(const float2*)&bias[c0];
            float2 o0 = {acc[mt][nt][0] + b2.x, acc[mt][nt][1] + b2.y};
            float2 o1 = {acc[mt][nt][2] + b2.x, acc[mt][nt][3] + b2.y};
            *(float2*)&C[r0 * Nc + c0] = o0;
            *(float2*)&C[(r0 + 8) * Nc + c0] = o1;
        }
    }
}

__global__ void __launch_bounds__(256) gemm_bf16split(
    const __nv_bfloat16* __restrict__ Ahi, const __nv_bfloat16* __restrict__ Alo,
    const __nv_bfloat16* __restrict__ Bhi, const __nv_bfloat16* __restrict__ Blo,
    const float* __restrict__ bias, float* __restrict__ C, int Nc, int K) {
    extern __shared__ __nv_bfloat16 smem[];
    gemm_body(smem, Ahi, Alo, Bhi, Blo, bias, C, Nc, K, blockIdx.y * 128, blockIdx.x * 64);
}

__global__ void __launch_bounds__(256) gemm_dual(
    const __nv_bfloat16* __restrict__ A0hi, const __nv_bfloat16* __restrict__ A0lo,
    const __nv_bfloat16* __restrict__ B0hi, const __nv_bfloat16* __restrict__ B0lo,
    const float* __restrict__ bias0, float* __restrict__ C0, int K0,
    const __nv_bfloat16* __restrict__ A1hi, const __nv_bfloat16* __restrict__ A1lo,
    const __nv_bfloat16* __restrict__ B1hi, const __nv_bfloat16* __restrict__ B1lo,
    const float* __restrict__ bias1, float* __restrict__ C1, int K1, int Nc) {
    extern __shared__ __nv_bfloat16 smem[];
    if (blockIdx.z == 0)
        gemm_body(smem, A0hi, A0lo, B0hi, B0lo, bias0, C0, Nc, K0, blockIdx.y * 128, blockIdx.x * 64);
    else
        gemm_body(smem, A1hi, A1lo, B1hi, B1lo, bias1, C1, Nc, K1, blockIdx.y * 128, blockIdx.x * 64);
}

// ---------------- sparse softmax attention + aggregate (low-sync rewrite) ----------------
__global__ void attn_agg2(const float* __restrict__ eT0, const float* __restrict__ eT1,
                          const float* __restrict__ msgcat,
                          const float* __restrict__ ac0_, const float* __restrict__ an0_,
                          const float* __restrict__ ac1_, const float* __restrict__ an1_,
                          const float* __restrict__ ba0, const float* __restrict__ ba1,
                          __nv_bfloat16* __restrict__ ahi, __nv_bfloat16* __restrict__ alo) {
    __shared__ int   jl[512];
    __shared__ float wl[512];
    __shared__ float sv[512 * 4];
    __shared__ int   cnts[64];
    __shared__ int   offs[64];
    __shared__ int   sE;
    __shared__ float wred[8 * 4];
    __shared__ float hred[4];

    int t = blockIdx.y;
    const float* eT   = t ? eT1 : eT0;
    const float* acur = t ? ac1_ : ac0_;
    const float* anb  = t ? an1_ : an0_;
    const float* ba   = t ? ba1 : ba0;
    const float* msg  = msgcat + t * 256;

    int i = blockIdx.x;
    int tid = threadIdx.x;
    int lane = tid & 31, wid = tid >> 5;
    int oidx = i * 512 + t * 256 + tid;

    // 1) read 8 candidate edges into registers; per-(q,warp) counts via ballot
    float v[8];
    unsigned m[8];
    bool f[8];
    const float* row = eT + (long)i * NN;
    #pragma unroll
    for (int q = 0; q < 8; q++) {
        float xv = row[q * 256 + tid];
        v[q] = xv;
        f[q] = (xv >= 0.f);
        m[q] = __ballot_sync(0xffffffffu, f[q]);
        if (lane == 0) cnts[q * 8 + wid] = __popc(m[q]);
    }
    __syncthreads();

    // 2) warp-0 shuffle scan of the 64 counts (order = j ascending -> deterministic)
    if (wid == 0) {
        int c0 = cnts[lane], c1 = cnts[lane + 32];
        int s0 = c0, s1 = c1;
        #pragma unroll
        for (int o = 1; o < 32; o <<= 1) {
            int u0 = __shfl_up_sync(0xffffffffu, s0, o); if (lane >= o) s0 += u0;
            int u1 = __shfl_up_sync(0xffffffffu, s1, o); if (lane >= o) s1 += u1;
        }
        int tot0 = __shfl_sync(0xffffffffu, s0, 31);
        offs[lane] = s0 - c0;
        offs[lane + 32] = tot0 + s1 - c1;
        if (lane == 31) sE = tot0 + s1;
    }
    __syncthreads();

    int E = sE;
    if (E == 0) {
        __nv_bfloat16 z = __float2bfloat16(0.f);
        ahi[oidx] = z;
        alo[oidx] = z;
        return;
    }
    if (E > 512) E = 512;

    // 3) compacted write
    unsigned lt = (1u << lane) - 1u;
    #pragma unroll
    for (int q = 0; q < 8; q++) {
        if (f[q]) {
            int pos = offs[q * 8 + wid] + __popc(m[q] & lt);
            if (pos < 512) { jl[pos] = q * 256 + tid; wl[pos] = v[q]; }
        }
    }
    __syncthreads();

    // 4) scores + thread-local max (only E entries touched)
    float ac[4], bah[4];
    #pragma unroll
    for (int h = 0; h < 4; h++) { ac[h] = acur[i * 4 + h]; bah[h] = ba[h]; }

    float mx[4] = {-INFINITY, -INFINITY, -INFINITY, -INFINITY};
    for (int e = tid; e < E; e += 256) {
        int j = jl[e]; float w = wl[e];
        float4 a4 = *(const float4*)&anb[j * 4];
        float an_[4] = {a4.x, a4.y, a4.z, a4.w};
        #pragma unroll
        for (int h = 0; h < 4; h++) {
            float s = an_[h] + ac[h] + bah[h];
            s = s > 0.f ? s : 0.2f * s;
            s *= w;
            sv[e * 4 + h] = s;
            mx[h] = fmaxf(mx[h], s);
        }
    }
    #pragma unroll
    for (int h = 0; h < 4; h++)
        #pragma unroll
        for (int o = 16; o > 0; o >>= 1)
            mx[h] = fmaxf(mx[h], __shfl_xor_sync(0xffffffffu, mx[h], o));
    if (lane == 0)
        #pragma unroll
        for (int h = 0; h < 4; h++) wred[wid * 4 + h] = mx[h];
    __syncthreads();
    if (tid < 4) {
        float mm = wred[tid];
        #pragma unroll
        for (int w2 = 1; w2 < 8; w2++) mm = fmaxf(mm, wred[w2 * 4 + tid]);
        hred[tid] = mm;
    }
    __syncthreads();
    float hm[4] = {hred[0], hred[1], hred[2], hred[3]};

    // 5) exp + thread-local sum
    float sm[4] = {0.f, 0.f, 0.f, 0.f};
    for (int e = tid; e < E; e += 256) {
        #pragma unroll
        for (int h = 0; h < 4; h++) {
            float u = expf(sv[e * 4 + h] - hm[h]);
            sv[e * 4 + h] = u;
            sm[h] += u;
        }
    }
    #pragma unroll
    for (int h = 0; h < 4; h++)
        #pragma unroll
        for (int o = 16; o > 0; o >>= 1)
            sm[h] += __shfl_xor_sync(0xffffffffu, sm[h], o);
    if (lane == 0)
        #pragma unroll
        for (int h = 0; h < 4; h++) wred[wid * 4 + h] = sm[h];
    __syncthreads();
    if (tid < 4) {
        float ss = wred[tid];
        #pragma unroll
        for (int w2 = 1; w2 < 8; w2++) ss += wred[w2 * 4 + tid];
        hred[tid] = ss;
    }
    __syncthreads();

    // 6) aggregate (normalization folded into the epilogue)
    int d = tid, h = d >> 6;
    float acc = 0.f;
    for (int e = 0; e < E; e++) acc += sv[e * 4 + h] * msg[jl[e] * 512 + d];
    acc *= (1.f / hred[h]);

    __nv_bfloat16 hb = __float2bfloat16(acc);
    ahi[oidx] = hb;
    alo[oidx] = __float2bfloat16(acc - __bfloat162float(hb));
}

// ---------------- GRU gates + LayerNorm ----------------
__global__ void gru_ln(const float* __restrict__ gi_, const float* __restrict__ gh_,
                       const float* __restrict__ x, const float* __restrict__ g,
                       const float* __restrict__ b, float* __restrict__ out) {
    int i = blockIdx.x, d = threadIdx.x;
    const float* gi = gi_ + i * 768;
    const float* gh = gh_ + i * 768;
    float r = 1.f / (1.f + expf(-(gi[d] + gh[d])));
    float z = 1.f / (1.f + expf(-(gi[256 + d] + gh[256 + d])));
    float n = tanhf(gi[512 + d] + r * gh[512 + d]);
    float hv = (1.f - z) * n + z * x[i * 256 + d];

    __shared__ float ssum[8], ssq[8];
    __shared__ float mu_s, rs_s;
    float s = hv, q = hv * hv;
    #pragma unroll
    for (int off = 16; off > 0; off >>= 1) {
        s += __shfl_down_sync(0xffffffffu, s, off);
        q += __shfl_down_sync(0xffffffffu, q, off);
    }
    int lane = d & 31, wid = d >> 5;
    if (lane == 0) { ssum[wid] = s; ssq[wid] = q; }
    __syncthreads();
    if (d == 0) {
        float S = 0.f, Q = 0.f;
        for (int w2 = 0; w2 < 8; w2++) { S += ssum[w2]; Q += ssq[w2]; }
        float mu = S / 256.f;
        float var = Q / 256.f - mu * mu;
        mu_s = mu;
        rs_s = rsqrtf(var + 1e-5f);
    }
    __syncthreads();
    out[i * 256 + d] = (hv - mu_s) * rs_s * g[d] + b[d];
}

// ---------------- host orchestration (single stream, 5 launches) ----------------
extern "C" void kernel_launch(void* const* d_in, const int* in_sizes, int n_in,
                              void* d_out, int out_size) {
    const float* x    = (const float*)d_in[0];
    const float* adj0 = (const float*)d_in[1];
    const float* adj1 = (const float*)d_in[2];
    const float* w0   = (const float*)d_in[3];
    const float* w1   = (const float*)d_in[4];
    const float* Wm0  = (const float*)d_in[5];
    const float* bm0  = (const float*)d_in[6];
    const float* Wa0  = (const float*)d_in[7];
    const float* ba0  = (const float*)d_in[8];
    const float* Wm1  = (const float*)d_in[9];
    const float* bm1  = (const float*)d_in[10];
    const float* Wa1  = (const float*)d_in[11];
    const float* ba1  = (const float*)d_in[12];
    const float* wih  = (const float*)d_in[13];
    const float* whh  = (const float*)d_in[14];
    const float* bih  = (const float*)d_in[15];
    const float* bhh  = (const float*)d_in[16];
    const float* lng  = (const float*)d_in[17];
    const float* lnb  = (const float*)d_in[18];
    float* out = (float*)d_out;

    float *msg, *e0, *e1, *gi, *gh, *ac0, *an0, *ac1, *an1, *bm;
    cudaGetSymbolAddress((void**)&msg, g_msg);
    cudaGetSymbolAddress((void**)&e0,  g_e0);
    cudaGetSymbolAddress((void**)&e1,  g_e1);
    cudaGetSymbolAddress((void**)&gi,  g_gi);
    cudaGetSymbolAddress((void**)&gh,  g_gh);
    cudaGetSymbolAddress((void**)&ac0, g_ac0);
    cudaGetSymbolAddress((void**)&an0, g_an0);
    cudaGetSymbolAddress((void**)&ac1, g_ac1);
    cudaGetSymbolAddress((void**)&an1, g_an1);
    cudaGetSymbolAddress((void**)&bm,  g_bm);

    __nv_bfloat16 *xhi, *xlo, *ahi, *alo, *wmhi, *wmlo, *wihhi, *wihlo, *whhhi, *whhlo;
    cudaGetSymbolAddress((void**)&xhi,   g_xhi);
    cudaGetSymbolAddress((void**)&xlo,   g_xlo);
    cudaGetSymbolAddress((void**)&ahi,   g_ahi);
    cudaGetSymbolAddress((void**)&alo,   g_alo);
    cudaGetSymbolAddress((void**)&wmhi,  g_wmhi);
    cudaGetSymbolAddress((void**)&wmlo,  g_wmlo);
    cudaGetSymbolAddress((void**)&wihhi, g_wihhi);
    cudaGetSymbolAddress((void**)&wihlo, g_wihlo);
    cudaGetSymbolAddress((void**)&whhhi, g_whhhi);
    cudaGetSymbolAddress((void**)&whhlo, g_whhlo);

    cudaFuncSetAttribute(gemm_bf16split,
                         cudaFuncAttributeMaxDynamicSharedMemorySize, GEMM_SMEM);
    cudaFuncSetAttribute(gemm_dual,
                         cudaFuncAttributeMaxDynamicSharedMemorySize, GEMM_SMEM);
    // maximize smem carveout so 3 CTAs (3 x 61,440B) fit per SM
    cudaFuncSetAttribute(gemm_bf16split,
                         cudaFuncAttributePreferredSharedMemoryCarveout, 100);
    cudaFuncSetAttribute(gemm_dual,
                         cudaFuncAttributePreferredSharedMemoryCarveout, 100);

    // 1) transpose+mask, acoef, bf16 splits, bias concat
    phase1<<<P1_GRID, 256>>>(x, adj0, w0, adj1, w1, Wa0, Wa1, Wm0, Wm1, wih, whh,
                             bm0, bm1, e0, e1, ac0, an0, ac1, an1,
                             xhi, xlo, wmhi, wmlo, wihhi, wihlo, whhhi, whhlo, bm);

    // 2) merged msg GEMM: [2048,512] = x @ [Wm0;Wm1]^T
    gemm_bf16split<<<dim3(8, 16), 256, GEMM_SMEM>>>(xhi, xlo, wmhi, wmlo, bm, msg, 512, 256);

    // 3) attention + aggregate (emits agg directly as bf16 hi/lo)
    attn_agg2<<<dim3(NN, 2), 256>>>(e0, e1, msg, ac0, an0, ac1, an1, ba0, ba1, ahi, alo);

    // 4) gi and gh GEMMs fused in one launch
    gemm_dual<<<dim3(12, 16, 2), 256, GEMM_SMEM>>>(
        ahi, alo, wihhi, wihlo, bih, gi, 512,
        xhi, xlo, whhhi, whhlo, bhh, gh, 256, 768);

    // 5) GRU gates + LayerNorm
    gru_ln<<<NN, 256>>>(gi, gh, x, lng, lnb, out);
}

// round 12
// speedup vs baseline: 1.3841x; 1.3841x over previous
#include <cuda_runtime.h>
#include <cuda_bf16.h>
#include <math.h>

#define NN 2048
#define DD 256

// ---------------- scratch (device globals; no allocation) ----------------
__device__ float g_msg[NN * 512];       // [msg0 | msg1] by column halves
__device__ float g_e0[NN * NN];
__device__ float g_e1[NN * NN];
__device__ float g_gi[NN * 768];
__device__ float g_gh[NN * 768];
__device__ float g_ac0[NN * 4];
__device__ float g_an0[NN * 4];
__device__ float g_ac1[NN * 4];
__device__ float g_an1[NN * 4];
__device__ float g_bm[512];             // [bm0 | bm1]

// bf16 split operands
__device__ __nv_bfloat16 g_xhi[NN * 256],  g_xlo[NN * 256];
__device__ __nv_bfloat16 g_ahi[NN * 512],  g_alo[NN * 512];      // agg in bf16 hi/lo
__device__ __nv_bfloat16 g_wmhi[512 * 256], g_wmlo[512 * 256];   // [Wm0 ; Wm1]
__device__ __nv_bfloat16 g_wihhi[768 * 512], g_wihlo[768 * 512];
__device__ __nv_bfloat16 g_whhhi[768 * 256], g_whhlo[768 * 256];

// ---------------- split helper ----------------
__device__ __forceinline__ void do_split(int blk, const float* __restrict__ src,
                                         __nv_bfloat16* __restrict__ hi,
                                         __nv_bfloat16* __restrict__ lo, int n4) {
    int i = blk * 256 + threadIdx.x;
    if (i >= n4) return;
    float4 v = ((const float4*)src)[i];
    float vv[4] = {v.x, v.y, v.z, v.w};
    __nv_bfloat16 h[4], l[4];
    #pragma unroll
    for (int k = 0; k < 4; k++) {
        h[k] = __float2bfloat16(vv[k]);
        l[k] = __float2bfloat16(vv[k] - __bfloat162float(h[k]));
    }
    *(uint2*)&hi[i * 4] = *(uint2*)h;
    *(uint2*)&lo[i * 4] = *(uint2*)l;
}

// ---------------- phase1 mega-kernel ----------------
#define P1_T    8192
#define P1_AC   (P1_T + 2048)
#define P1_SPX  (P1_AC)
#define P1_SPW0 (P1_SPX + 512)
#define P1_SPW1 (P1_SPW0 + 64)
#define P1_SPIH (P1_SPW1 + 64)
#define P1_SPHH (P1_SPIH + 384)
#define P1_BM   (P1_SPHH + 192)
#define P1_GRID (P1_BM + 1)

__global__ void phase1(const float* __restrict__ x,
                       const float* __restrict__ adj0, const float* __restrict__ w0,
                       const float* __restrict__ adj1, const float* __restrict__ w1,
                       const float* __restrict__ Wa0, const float* __restrict__ Wa1,
                       const float* __restrict__ Wm0, const float* __restrict__ Wm1,
                       const float* __restrict__ wih, const float* __restrict__ whh,
                       const float* __restrict__ bm0, const float* __restrict__ bm1,
                       float* __restrict__ e0, float* __restrict__ e1,
                       float* __restrict__ ac0, float* __restrict__ an0,
                       float* __restrict__ ac1, float* __restrict__ an1,
                       __nv_bfloat16* __restrict__ xhi, __nv_bfloat16* __restrict__ xlo,
                       __nv_bfloat16* __restrict__ wmhi, __nv_bfloat16* __restrict__ wmlo,
                       __nv_bfloat16* __restrict__ wihhi, __nv_bfloat16* __restrict__ wihlo,
                       __nv_bfloat16* __restrict__ whhhi, __nv_bfloat16* __restrict__ whhlo,
                       float* __restrict__ bm) {
    int b = blockIdx.x;
    int tid = threadIdx.x;

    if (b < P1_T) {
        int t = b >> 12;
        int rem = b & 4095;
        int i0 = (rem & 63) * 32, j0 = (rem >> 6) * 32;
        const float* adj = t ? adj1 : adj0;
        const float* w   = t ? w1   : w0;
        float*       e   = t ? e1   : e0;
        __shared__ float tile[32][33];
        int tx = tid & 31, ty = tid >> 5;
        #pragma unroll
        for (int r = 0; r < 4; r++) {
            int j = j0 + ty + r * 8;
            int idx = j * NN + i0 + tx;
            float a = adj[idx];
            tile[ty + r * 8][tx] = (a != 0.f) ? w[idx] : -1.0f;
        }
        __syncthreads();
        #pragma unroll
        for (int r = 0; r < 4; r++) {
            int i = i0 + ty + r * 8;
            e[i * NN + j0 + tx] = tile[tx][ty + r * 8];
        }
        return;
    }
    if (b < P1_AC) {
        int i = b - P1_T;
        __shared__ float xs[256];
        xs[tid] = x[i * 256 + tid];
        __syncthreads();
        int lane = tid & 31, wid = tid >> 5;
        #pragma unroll
        for (int oo = 0; oo < 2; oo++) {
            int o = wid + oo * 8;
            int t = o >> 3, rem = o & 7;
            int half = rem >> 2, h = rem & 3;
            const float* Wa = t ? Wa1 : Wa0;
            const float* row = Wa + h * 512 + half * 256;
            float s = 0.f;
            #pragma unroll
            for (int k = lane; k < 256; k += 32) s += xs[k] * row[k];
            #pragma unroll
            for (int off = 16; off > 0; off >>= 1) s += __shfl_down_sync(0xffffffffu, s, off);
            if (lane == 0) {
                float* dst = half ? (t ? an1 : an0) : (t ? ac1 : ac0);
                dst[i * 4 + h] = s;
            }
        }
        return;
    }
    if (b < P1_SPW0) { do_split(b - P1_SPX,  x,   xhi,   xlo,   NN * 256 / 4); return; }
    if (b < P1_SPW1) { do_split(b - P1_SPW0, Wm0, wmhi,  wmlo,  256 * 256 / 4); return; }
    if (b < P1_SPIH) { do_split(b - P1_SPW1, Wm1, wmhi + 256 * 256, wmlo + 256 * 256, 256 * 256 / 4); return; }
    if (b < P1_SPHH) { do_split(b - P1_SPIH, wih, wihhi, wihlo, 768 * 512 / 4); return; }
    if (b < P1_BM)   { do_split(b - P1_SPHH, whh, whhhi, whhlo, 768 * 256 / 4); return; }
    bm[tid] = bm0[tid];
    bm[tid + 256] = bm1[tid];
}

// ---------------- mma helper ----------------
__device__ __forceinline__ void mma16816(float* c, const unsigned* a, const unsigned* b) {
    asm volatile(
        "mma.sync.aligned.m16n8k16.row.col.f32.bf16.bf16.f32 "
        "{%0,%1,%2,%3},{%4,%5,%6,%7},{%8,%9},{%0,%1,%2,%3};"
        : "+f"(c[0]), "+f"(c[1]), "+f"(c[2]), "+f"(c[3])
        : "r"(a[0]), "r"(a[1]), "r"(a[2]), "r"(a[3]), "r"(b[0]), "r"(b[1]));
}

// ---------------- tensor-core GEMM body: BM=64, BN=64, BK=32, 8 warps (2x4) ----------
// warp tile m32 x n16; scalar-LDS fragment loads (proven R8 pattern)
#define AST 40
#define TSZ (64 * AST)                    // one 64x32 tile (elems, padded)
#define GEMM_SMEM (8 * TSZ * 2)           // A(2st x hi/lo) + B(2st x hi/lo), bytes = 40960

__device__ __forceinline__ void gemm_body(
    __nv_bfloat16* smem,
    const __nv_bfloat16* __restrict__ Ahi, const __nv_bfloat16* __restrict__ Alo,
    const __nv_bfloat16* __restrict__ Bhi, const __nv_bfloat16* __restrict__ Blo,
    const float* __restrict__ bias, float* __restrict__ C,
    int Nc, int K, int m0, int n0) {
    __nv_bfloat16* sA = smem;             // [st][hi/lo][TSZ]
    __nv_bfloat16* sB = smem + 4 * TSZ;

    int tid = threadIdx.x, lane = tid & 31, wid = tid >> 5;
    int wr = wid >> 2, wc = wid & 3;      // 2 x 4 warps
    int g = lane >> 2, tq = lane & 3;

    float acc[2][2][4] = {};

    auto issue = [&](int kk, int st) {
        int r = tid >> 2, c = (tid & 3) * 8;    // 64 rows x 4 chunks of 8 bf16
        unsigned dah = (unsigned)__cvta_generic_to_shared(&sA[(st * 2 + 0) * TSZ + r * AST + c]);
        unsigned dal = (unsigned)__cvta_generic_to_shared(&sA[(st * 2 + 1) * TSZ + r * AST + c]);
        unsigned dbh = (unsigned)__cvta_generic_to_shared(&sB[(st * 2 + 0) * TSZ + r * AST + c]);
        unsigned dbl = (unsigned)__cvta_generic_to_shared(&sB[(st * 2 + 1) * TSZ + r * AST + c]);
        asm volatile("cp.async.cg.shared.global [%0],[%1],16;" :: "r"(dah), "l"(&Ahi[(m0 + r) * K + kk + c]));
        asm volatile("cp.async.cg.shared.global [%0],[%1],16;" :: "r"(dal), "l"(&Alo[(m0 + r) * K + kk + c]));
        asm volatile("cp.async.cg.shared.global [%0],[%1],16;" :: "r"(dbh), "l"(&Bhi[(n0 + r) * K + kk + c]));
        asm volatile("cp.async.cg.shared.global [%0],[%1],16;" :: "r"(dbl), "l"(&Blo[(n0 + r) * K + kk + c]));
    };

    auto compute = [&](int st) {
        const __nv_bfloat16* Ah = sA + (st * 2 + 0) * TSZ;
        const __nv_bfloat16* Al = sA + (st * 2 + 1) * TSZ;
        const __nv_bfloat16* Bh = sB + (st * 2 + 0) * TSZ;
        const __nv_bfloat16* Bl = sB + (st * 2 + 1) * TSZ;
        #pragma unroll
        for (int k16 = 0; k16 < 32; k16 += 16) {
            unsigned ahi[2][4], alo[2][4], bhi[2][2], blo[2][2];
            #pragma unroll
            for (int mt = 0; mt < 2; mt++) {
                int ra = wr * 32 + mt * 16 + g;
                const __nv_bfloat16* p = &Ah[ra * AST + k16 + tq * 2];
                ahi[mt][0] = *(const unsigned*)p;
                ahi[mt][1] = *(const unsigned*)(p + 8 * AST);
                ahi[mt][2] = *(const unsigned*)(p + 8);
                ahi[mt][3] = *(const unsigned*)(p + 8 * AST + 8);
                const __nv_bfloat16* q = &Al[ra * AST + k16 + tq * 2];
                alo[mt][0] = *(const unsigned*)q;
                alo[mt][1] = *(const unsigned*)(q + 8 * AST);
                alo[mt][2] = *(const unsigned*)(q + 8);
                alo[mt][3] = *(const unsigned*)(q + 8 * AST + 8);
            }
            #pragma unroll
            for (int nt = 0; nt < 2; nt++) {
                int cb = wc * 16 + nt * 8 + g;
                const __nv_bfloat16* p = &Bh[cb * AST + k16 + tq * 2];
                bhi[nt][0] = *(const unsigned*)p;
                bhi[nt][1] = *(const unsigned*)(p + 8);
                const __nv_bfloat16* q = &Bl[cb * AST + k16 + tq * 2];
                blo[nt][0] = *(const unsigned*)q;
                blo[nt][1] = *(const unsigned*)(q + 8);
            }
            #pragma unroll
            for (int mt = 0; mt < 2; mt++)
                #pragma unroll
                for (int nt = 0; nt < 2; nt++) {
                    mma16816(acc[mt][nt], ahi[mt], bhi[nt]);
                    mma16816(acc[mt][nt], ahi[mt], blo[nt]);
                    mma16816(acc[mt][nt], alo[mt], bhi[nt]);
                }
        }
    };

    int nk = K / 32;
    issue(0, 0);
    asm volatile("cp.async.commit_group;");
    for (int kt = 0; kt < nk; kt++) {
        if (kt + 1 < nk) {
            issue((kt + 1) * 32, (kt + 1) & 1);
            asm volatile("cp.async.commit_group;");
            asm volatile("cp.async.wait_group 1;");
        } else {
            asm volatile("cp.async.wait_group 0;");
        }
        __syncthreads();
        compute(kt & 1);
        __syncthreads();
    }

    #pragma unroll
    for (int mt = 0; mt < 2; mt++) {
        int r0 = m0 + wr * 32 + mt * 16 + g;
        #pragma unroll
        for (int nt = 0; nt < 2; nt++) {
            int c0 = n0 + wc * 16 + nt * 8 + tq * 2;
            float2 b2 = *(const float2*)&bias[c0];
            float2 o0 = {acc[mt][nt][0] + b2.x, acc[mt][nt][1] + b2.y};
            float2 o1 = {acc[mt][nt][2] + b2.x, acc[mt][nt][3] + b2.y};
            *(float2*)&C[r0 * Nc + c0] = o0;
            *(float2*)&C[(r0 + 8) * Nc + c0] = o1;
        }
    }
}

__global__ void __launch_bounds__(256) gemm_bf16split(
    const __nv_bfloat16* __restrict__ Ahi, const __nv_bfloat16* __restrict__ Alo,
    const __nv_bfloat16* __restrict__ Bhi, const __nv_bfloat16* __restrict__ Blo,
    const float* __restrict__ bias, float* __restrict__ C, int Nc, int K) {
    extern __shared__ __nv_bfloat16 smem[];
    gemm_body(smem, Ahi, Alo, Bhi, Blo, bias, C, Nc, K, blockIdx.y * 64, blockIdx.x * 64);
}

__global__ void __launch_bounds__(256) gemm_dual(
    const __nv_bfloat16* __restrict__ A0hi, const __nv_bfloat16* __restrict__ A0lo,
    const __nv_bfloat16* __restrict__ B0hi, const __nv_bfloat16* __restrict__ B0lo,
    const float* __restrict__ bias0, float* __restrict__ C0, int K0,
    const __nv_bfloat16* __restrict__ A1hi, const __nv_bfloat16* __restrict__ A1lo,
    const __nv_bfloat16* __restrict__ B1hi, const __nv_bfloat16* __restrict__ B1lo,
    const float* __restrict__ bias1, float* __restrict__ C1, int K1, int Nc) {
    extern __shared__ __nv_bfloat16 smem[];
    if (blockIdx.z == 0)
        gemm_body(smem, A0hi, A0lo, B0hi, B0lo, bias0, C0, Nc, K0, blockIdx.y * 64, blockIdx.x * 64);
    else
        gemm_body(smem, A1hi, A1lo, B1hi, B1lo, bias1, C1, Nc, K1, blockIdx.y * 64, blockIdx.x * 64);
}

// ---------------- sparse softmax attention + aggregate (low-sync, MLP-unrolled) -------
__global__ void attn_agg2(const float* __restrict__ eT0, const float* __restrict__ eT1,
                          const float* __restrict__ msgcat,
                          const float* __restrict__ ac0_, const float* __restrict__ an0_,
                          const float* __restrict__ ac1_, const float* __restrict__ an1_,
                          const float* __restrict__ ba0, const float* __restrict__ ba1,
                          __nv_bfloat16* __restrict__ ahi, __nv_bfloat16* __restrict__ alo) {
    __shared__ int   jl[512];
    __shared__ float wl[512];
    __shared__ float sv[512 * 4];
    __shared__ int   cnts[64];
    __shared__ int   offs[64];
    __shared__ int   sE;
    __shared__ float wred[8 * 4];
    __shared__ float hred[4];

    int t = blockIdx.y;
    const float* eT   = t ? eT1 : eT0;
    const float* acur = t ? ac1_ : ac0_;
    const float* anb  = t ? an1_ : an0_;
    const float* ba   = t ? ba1 : ba0;
    const float* msg  = msgcat + t * 256;

    int i = blockIdx.x;
    int tid = threadIdx.x;
    int lane = tid & 31, wid = tid >> 5;
    int oidx = i * 512 + t * 256 + tid;

    // 1) read 8 candidate edges; per-(q,warp) counts via ballot
    float v[8];
    unsigned m[8];
    bool f[8];
    const float* row = eT + (long)i * NN;
    #pragma unroll
    for (int q = 0; q < 8; q++) {
        float xv = row[q * 256 + tid];
        v[q] = xv;
        f[q] = (xv >= 0.f);
        m[q] = __ballot_sync(0xffffffffu, f[q]);
        if (lane == 0) cnts[q * 8 + wid] = __popc(m[q]);
    }
    __syncthreads();

    // 2) warp-0 shuffle scan of 64 counts (j-ascending order -> deterministic)
    if (wid == 0) {
        int c0 = cnts[lane], c1 = cnts[lane + 32];
        int s0 = c0, s1 = c1;
        #pragma unroll
        for (int o = 1; o < 32; o <<= 1) {
            int u0 = __shfl_up_sync(0xffffffffu, s0, o); if (lane >= o) s0 += u0;
            int u1 = __shfl_up_sync(0xffffffffu, s1, o); if (lane >= o) s1 += u1;
        }
        int tot0 = __shfl_sync(0xffffffffu, s0, 31);
        offs[lane] = s0 - c0;
        offs[lane + 32] = tot0 + s1 - c1;
        if (lane == 31) sE = tot0 + s1;
    }
    __syncthreads();

    int E = sE;
    if (E == 0) {
        __nv_bfloat16 z = __float2bfloat16(0.f);
        ahi[oidx] = z;
        alo[oidx] = z;
        return;
    }
    if (E > 512) E = 512;

    // 3) compacted write
    unsigned lt = (1u << lane) - 1u;
    #pragma unroll
    for (int q = 0; q < 8; q++) {
        if (f[q]) {
            int pos = offs[q * 8 + wid] + __popc(m[q] & lt);
            if (pos < 512) { jl[pos] = q * 256 + tid; wl[pos] = v[q]; }
        }
    }
    __syncthreads();

    // 4) scores + thread-local max
    float ac[4], bah[4];
    #pragma unroll
    for (int h = 0; h < 4; h++) { ac[h] = acur[i * 4 + h]; bah[h] = ba[h]; }

    float mx[4] = {-INFINITY, -INFINITY, -INFINITY, -INFINITY};
    for (int e = tid; e < E; e += 256) {
        int j = jl[e]; float w = wl[e];
        float4 a4 = *(const float4*)&anb[j * 4];
        float an_[4] = {a4.x, a4.y, a4.z, a4.w};
        #pragma unroll
        for (int h = 0; h < 4; h++) {
            float s = an_[h] + ac[h] + bah[h];
            s = s > 0.f ? s : 0.2f * s;
            s *= w;
            sv[e * 4 + h] = s;
            mx[h] = fmaxf(mx[h], s);
        }
    }
    #pragma unroll
    for (int h = 0; h < 4; h++)
        #pragma unroll
        for (int o = 16; o > 0; o >>= 1)
            mx[h] = fmaxf(mx[h], __shfl_xor_sync(0xffffffffu, mx[h], o));
    if (lane == 0)
        #pragma unroll
        for (int h = 0; h < 4; h++) wred[wid * 4 + h] = mx[h];
    __syncthreads();
    if (tid < 4) {
        float mm = wred[tid];
        #pragma unroll
        for (int w2 = 1; w2 < 8; w2++) mm = fmaxf(mm, wred[w2 * 4 + tid]);
        hred[tid] = mm;
    }
    __syncthreads();
    float hm[4] = {hred[0], hred[1], hred[2], hred[3]};

    // 5) exp + thread-local sum
    float sm[4] = {0.f, 0.f, 0.f, 0.f};
    for (int e = tid; e < E; e += 256) {
        #pragma unroll
        for (int h = 0; h < 4; h++) {
            float u = expf(sv[e * 4 + h] - hm[h]);
            sv[e * 4 + h] = u;
            sm[h] += u;
        }
    }
    #pragma unroll
    for (int h = 0; h < 4; h++)
        #pragma unroll
        for (int o = 16; o > 0; o >>= 1)
            sm[h] += __shfl_xor_sync(0xffffffffu, sm[h], o);
    if (lane == 0)
        #pragma unroll
        for (int h = 0; h < 4; h++) wred[wid * 4 + h] = sm[h];
    __syncthreads();
    if (tid < 4) {
        float ss = wred[tid];
        #pragma unroll
        for (int w2 = 1; w2 < 8; w2++) ss += wred[w2 * 4 + tid];
        hred[tid] = ss;
    }
    __syncthreads();

    // 6) aggregate, 4x unrolled for MLP; normalization folded in
    int d = tid, h = d >> 6;
    float acc = 0.f;
    int e = 0;
    for (; e + 4 <= E; e += 4) {
        int j0 = jl[e], j1 = jl[e + 1], j2 = jl[e + 2], j3 = jl[e + 3];
        float s0 = sv[(e) * 4 + h], s1 = sv[(e + 1) * 4 + h];
        float s2 = sv[(e + 2) * 4 + h], s3 = sv[(e + 3) * 4 + h];
        float m0_ = msg[j0 * 512 + d];
        float m1_ = msg[j1 * 512 + d];
        float m2_ = msg[j2 * 512 + d];
        float m3_ = msg[j3 * 512 + d];
        acc += s0 * m0_ + s1 * m1_ + s2 * m2_ + s3 * m3_;
    }
    for (; e < E; e++) acc += sv[e * 4 + h] * msg[jl[e] * 512 + d];
    acc *= (1.f / hred[h]);

    __nv_bfloat16 hb = __float2bfloat16(acc);
    ahi[oidx] = hb;
    alo[oidx] = __float2bfloat16(acc - __bfloat162float(hb));
}

// ---------------- GRU gates + LayerNorm ----------------
__global__ void gru_ln(const float* __restrict__ gi_, const float* __restrict__ gh_,
                       const float* __restrict__ x, const float* __restrict__ g,
                       const float* __restrict__ b, float* __restrict__ out) {
    int i = blockIdx.x, d = threadIdx.x;
    const float* gi = gi_ + i * 768;
    const float* gh = gh_ + i * 768;
    float r = 1.f / (1.f + expf(-(gi[d] + gh[d])));
    float z = 1.f / (1.f + expf(-(gi[256 + d] + gh[256 + d])));
    float n = tanhf(gi[512 + d] + r * gh[512 + d]);
    float hv = (1.f - z) * n + z * x[i * 256 + d];

    __shared__ float ssum[8], ssq[8];
    __shared__ float mu_s, rs_s;
    float s = hv, q = hv * hv;
    #pragma unroll
    for (int off = 16; off > 0; off >>= 1) {
        s += __shfl_down_sync(0xffffffffu, s, off);
        q += __shfl_down_sync(0xffffffffu, q, off);
    }
    int lane = d & 31, wid = d >> 5;
    if (lane == 0) { ssum[wid] = s; ssq[wid] = q; }
    __syncthreads();
    if (d == 0) {
        float S = 0.f, Q = 0.f;
        for (int w2 = 0; w2 < 8; w2++) { S += ssum[w2]; Q += ssq[w2]; }
        float mu = S / 256.f;
        float var = Q / 256.f - mu * mu;
        mu_s = mu;
        rs_s = rsqrtf(var + 1e-5f);
    }
    __syncthreads();
    out[i * 256 + d] = (hv - mu_s) * rs_s * g[d] + b[d];
}

// ---------------- host orchestration (single stream, 5 launches) ----------------
extern "C" void kernel_launch(void* const* d_in, const int* in_sizes, int n_in,
                              void* d_out, int out_size) {
    const float* x    = (const float*)d_in[0];
    const float* adj0 = (const float*)d_in[1];
    const float* adj1 = (const float*)d_in[2];
    const float* w0   = (const float*)d_in[3];
    const float* w1   = (const float*)d_in[4];
    const float* Wm0  = (const float*)d_in[5];
    const float* bm0  = (const float*)d_in[6];
    const float* Wa0  = (const float*)d_in[7];
    const float* ba0  = (const float*)d_in[8];
    const float* Wm1  = (const float*)d_in[9];
    const float* bm1  = (const float*)d_in[10];
    const float* Wa1  = (const float*)d_in[11];
    const float* ba1  = (const float*)d_in[12];
    const float* wih  = (const float*)d_in[13];
    const float* whh  = (const float*)d_in[14];
    const float* bih  = (const float*)d_in[15];
    const float* bhh  = (const float*)d_in[16];
    const float* lng  = (const float*)d_in[17];
    const float* lnb  = (const float*)d_in[18];
    float* out = (float*)d_out;

    float *msg, *e0, *e1, *gi, *gh, *ac0, *an0, *ac1, *an1, *bm;
    cudaGetSymbolAddress((void**)&msg, g_msg);
    cudaGetSymbolAddress((void**)&e0,  g_e0);
    cudaGetSymbolAddress((void**)&e1,  g_e1);
    cudaGetSymbolAddress((void**)&gi,  g_gi);
    cudaGetSymbolAddress((void**)&gh,  g_gh);
    cudaGetSymbolAddress((void**)&ac0, g_ac0);
    cudaGetSymbolAddress((void**)&an0, g_an0);
    cudaGetSymbolAddress((void**)&ac1, g_ac1);
    cudaGetSymbolAddress((void**)&an1, g_an1);
    cudaGetSymbolAddress((void**)&bm,  g_bm);

    __nv_bfloat16 *xhi, *xlo, *ahi, *alo, *wmhi, *wmlo, *wihhi, *wihlo, *whhhi, *whhlo;
    cudaGetSymbolAddress((void**)&xhi,   g_xhi);
    cudaGetSymbolAddress((void**)&xlo,   g_xlo);
    cudaGetSymbolAddress((void**)&ahi,   g_ahi);
    cudaGetSymbolAddress((void**)&alo,   g_alo);
    cudaGetSymbolAddress((void**)&wmhi,  g_wmhi);
    cudaGetSymbolAddress((void**)&wmlo,  g_wmlo);
    cudaGetSymbolAddress((void**)&wihhi, g_wihhi);
    cudaGetSymbolAddress((void**)&wihlo, g_wihlo);
    cudaGetSymbolAddress((void**)&whhhi, g_whhhi);
    cudaGetSymbolAddress((void**)&whhlo, g_whhlo);

    cudaFuncSetAttribute(gemm_bf16split,
                         cudaFuncAttributeMaxDynamicSharedMemorySize, GEMM_SMEM);
    cudaFuncSetAttribute(gemm_dual,
                         cudaFuncAttributeMaxDynamicSharedMemorySize, GEMM_SMEM);

    // 1) transpose+mask, acoef, bf16 splits, bias concat
    phase1<<<P1_GRID, 256>>>(x, adj0, w0, adj1, w1, Wa0, Wa1, Wm0, Wm1, wih, whh,
                             bm0, bm1, e0, e1, ac0, an0, ac1, an1,
                             xhi, xlo, wmhi, wmlo, wihhi, wihlo, whhhi, whhlo, bm);

    // 2) merged msg GEMM: [2048,512] = x @ [Wm0;Wm1]^T   (64x64 tiles -> 256 blocks)
    gemm_bf16split<<<dim3(8, 32), 256, GEMM_SMEM>>>(xhi, xlo, wmhi, wmlo, bm, msg, 512, 256);

    // 3) attention + aggregate (emits agg directly as bf16 hi/lo)
    attn_agg2<<<dim3(NN, 2), 256>>>(e0, e1, msg, ac0, an0, ac1, an1, ba0, ba1, ahi, alo);

    // 4) gi and gh GEMMs fused, 64x64 tiles -> 768 blocks
    gemm_dual<<<dim3(12, 32, 2), 256, GEMM_SMEM>>>(
        ahi, alo, wihhi, wihlo, bih, gi, 512,
        xhi, xlo, whhhi, whhlo, bhh, gh, 256, 768);

    // 5) GRU gates + LayerNorm
    gru_ln<<<NN, 256>>>(gi, gh, x, lng, lnb, out);
}

// round 16
// speedup vs baseline: 1.4005x; 1.0118x over previous
#include <cuda_runtime.h>
#include <cuda_bf16.h>
#include <math.h>

#define NN 2048
#define DD 256

// ---------------- scratch (device globals; no allocation) ----------------
__device__ float g_msg[NN * 512];       // [msg0 | msg1] by column halves
__device__ float g_e0[NN * NN];
__device__ float g_e1[NN * NN];
__device__ float g_gi[NN * 768];
__device__ float g_gh[NN * 768];
__device__ float g_ac0[NN * 4];
__device__ float g_an0[NN * 4];
__device__ float g_ac1[NN * 4];
__device__ float g_an1[NN * 4];
__device__ float g_bm[512];             // [bm0 | bm1]

// bf16 split operands
__device__ __nv_bfloat16 g_xhi[NN * 256],  g_xlo[NN * 256];
__device__ __nv_bfloat16 g_ahi[NN * 512],  g_alo[NN * 512];      // agg in bf16 hi/lo
__device__ __nv_bfloat16 g_wmhi[512 * 256], g_wmlo[512 * 256];   // [Wm0 ; Wm1]
__device__ __nv_bfloat16 g_wihhi[768 * 512], g_wihlo[768 * 512];
__device__ __nv_bfloat16 g_whhhi[768 * 256], g_whhlo[768 * 256];

// ---------------- split helper ----------------
__device__ __forceinline__ void do_split(int blk, const float* __restrict__ src,
                                         __nv_bfloat16* __restrict__ hi,
                                         __nv_bfloat16* __restrict__ lo, int n4) {
    int i = blk * 256 + threadIdx.x;
    if (i >= n4) return;
    float4 v = ((const float4*)src)[i];
    float vv[4] = {v.x, v.y, v.z, v.w};
    __nv_bfloat16 h[4], l[4];
    #pragma unroll
    for (int k = 0; k < 4; k++) {
        h[k] = __float2bfloat16(vv[k]);
        l[k] = __float2bfloat16(vv[k] - __bfloat162float(h[k]));
    }
    *(uint2*)&hi[i * 4] = *(uint2*)h;
    *(uint2*)&lo[i * 4] = *(uint2*)l;
}

// ---------------- phase1 mega-kernel ----------------
#define P1_T    8192
#define P1_AC   (P1_T + 2048)
#define P1_SPX  (P1_AC)
#define P1_SPW0 (P1_SPX + 512)
#define P1_SPW1 (P1_SPW0 + 64)
#define P1_SPIH (P1_SPW1 + 64)
#define P1_SPHH (P1_SPIH + 384)
#define P1_BM   (P1_SPHH + 192)
#define P1_GRID (P1_BM + 1)

__global__ void phase1(const float* __restrict__ x,
                       const float* __restrict__ adj0, const float* __restrict__ w0,
                       const float* __restrict__ adj1, const float* __restrict__ w1,
                       const float* __restrict__ Wa0, const float* __restrict__ Wa1,
                       const float* __restrict__ Wm0, const float* __restrict__ Wm1,
                       const float* __restrict__ wih, const float* __restrict__ whh,
                       const float* __restrict__ bm0, const float* __restrict__ bm1,
                       float* __restrict__ e0, float* __restrict__ e1,
                       float* __restrict__ ac0, float* __restrict__ an0,
                       float* __restrict__ ac1, float* __restrict__ an1,
                       __nv_bfloat16* __restrict__ xhi, __nv_bfloat16* __restrict__ xlo,
                       __nv_bfloat16* __restrict__ wmhi, __nv_bfloat16* __restrict__ wmlo,
                       __nv_bfloat16* __restrict__ wihhi, __nv_bfloat16* __restrict__ wihlo,
                       __nv_bfloat16* __restrict__ whhhi, __nv_bfloat16* __restrict__ whhlo,
                       float* __restrict__ bm) {
    int b = blockIdx.x;
    int tid = threadIdx.x;

    if (b < P1_T) {
        int t = b >> 12;
        int rem = b & 4095;
        int i0 = (rem & 63) * 32, j0 = (rem >> 6) * 32;
        const float* adj = t ? adj1 : adj0;
        const float* w   = t ? w1   : w0;
        float*       e   = t ? e1   : e0;
        __shared__ float tile[32][33];
        int tx = tid & 31, ty = tid >> 5;
        #pragma unroll
        for (int r = 0; r < 4; r++) {
            int j = j0 + ty + r * 8;
            int idx = j * NN + i0 + tx;
            float a = adj[idx];
            tile[ty + r * 8][tx] = (a != 0.f) ? w[idx] : -1.0f;
        }
        __syncthreads();
        #pragma unroll
        for (int r = 0; r < 4; r++) {
            int i = i0 + ty + r * 8;
            e[i * NN + j0 + tx] = tile[tx][ty + r * 8];
        }
        return;
    }
    if (b < P1_AC) {
        int i = b - P1_T;
        __shared__ float xs[256];
        xs[tid] = x[i * 256 + tid];
        __syncthreads();
        int lane = tid & 31, wid = tid >> 5;
        #pragma unroll
        for (int oo = 0; oo < 2; oo++) {
            int o = wid + oo * 8;
            int t = o >> 3, rem = o & 7;
            int half = rem >> 2, h = rem & 3;
            const float* Wa = t ? Wa1 : Wa0;
            const float* row = Wa + h * 512 + half * 256;
            float s = 0.f;
            #pragma unroll
            for (int k = lane; k < 256; k += 32) s += xs[k] * row[k];
            #pragma unroll
            for (int off = 16; off > 0; off >>= 1) s += __shfl_down_sync(0xffffffffu, s, off);
            if (lane == 0) {
                float* dst = half ? (t ? an1 : an0) : (t ? ac1 : ac0);
                dst[i * 4 + h] = s;
            }
        }
        return;
    }
    if (b < P1_SPW0) { do_split(b - P1_SPX,  x,   xhi,   xlo,   NN * 256 / 4); return; }
    if (b < P1_SPW1) { do_split(b - P1_SPW0, Wm0, wmhi,  wmlo,  256 * 256 / 4); return; }
    if (b < P1_SPIH) { do_split(b - P1_SPW1, Wm1, wmhi + 256 * 256, wmlo + 256 * 256, 256 * 256 / 4); return; }
    if (b < P1_SPHH) { do_split(b - P1_SPIH, wih, wihhi, wihlo, 768 * 512 / 4); return; }
    if (b < P1_BM)   { do_split(b - P1_SPHH, whh, whhhi, whhlo, 768 * 256 / 4); return; }
    bm[tid] = bm0[tid];
    bm[tid + 256] = bm1[tid];
}

// ---------------- mma helper ----------------
__device__ __forceinline__ void mma16816(float* c, const unsigned* a, const unsigned* b) {
    asm volatile(
        "mma.sync.aligned.m16n8k16.row.col.f32.bf16.bf16.f32 "
        "{%0,%1,%2,%3},{%4,%5,%6,%7},{%8,%9},{%0,%1,%2,%3};"
        : "+f"(c[0]), "+f"(c[1]), "+f"(c[2]), "+f"(c[3])
        : "r"(a[0]), "r"(a[1]), "r"(a[2]), "r"(a[3]), "r"(b[0]), "r"(b[1]));
}

// ---------------- tensor-core GEMM body: BM=64, BN=64, BK=32, 8 warps (2x4) ----------
// 3-stage cp.async pipeline, ONE __syncthreads per K-tile.
#define AST 40
#define TSZ (64 * AST)                    // one 64x32 tile (elems, padded)
#define GEMM_SMEM (12 * TSZ * 2)          // 3 stages x (A hi/lo + B hi/lo) = 61440 B

__device__ __forceinline__ void gemm_body(
    __nv_bfloat16* smem,
    const __nv_bfloat16* __restrict__ Ahi, const __nv_bfloat16* __restrict__ Alo,
    const __nv_bfloat16* __restrict__ Bhi, const __nv_bfloat16* __restrict__ Blo,
    const float* __restrict__ bias, float* __restrict__ C,
    int Nc, int K, int m0, int n0) {
    __nv_bfloat16* sA = smem;             // [st][hi/lo][TSZ], st in {0,1,2}
    __nv_bfloat16* sB = smem + 6 * TSZ;

    int tid = threadIdx.x, lane = tid & 31, wid = tid >> 5;
    int wr = wid >> 2, wc = wid & 3;      // 2 x 4 warps
    int g = lane >> 2, tq = lane & 3;

    float acc[2][2][4] = {};

    // per-thread load coordinates (constant)
    int lr = tid >> 2, lc = (tid & 3) * 8;
    unsigned sbase = (unsigned)__cvta_generic_to_shared(smem);
    unsigned loff = (unsigned)((lr * AST + lc) * 2);
    const __nv_bfloat16* gA_hi = Ahi + (m0 + lr) * K + lc;
    const __nv_bfloat16* gA_lo = Alo + (m0 + lr) * K + lc;
    const __nv_bfloat16* gB_hi = Bhi + (n0 + lr) * K + lc;
    const __nv_bfloat16* gB_lo = Blo + (n0 + lr) * K + lc;

    auto issue = [&](int kk, int st) {
        unsigned dah = sbase + (st * 2 + 0) * (TSZ * 2) + loff;
        unsigned dal = sbase + (st * 2 + 1) * (TSZ * 2) + loff;
        unsigned dbh = sbase + (6 + st * 2 + 0) * (TSZ * 2) + loff;
        unsigned dbl = sbase + (6 + st * 2 + 1) * (TSZ * 2) + loff;
        asm volatile("cp.async.cg.shared.global [%0],[%1],16;" :: "r"(dah), "l"(gA_hi + kk));
        asm volatile("cp.async.cg.shared.global [%0],[%1],16;" :: "r"(dal), "l"(gA_lo + kk));
        asm volatile("cp.async.cg.shared.global [%0],[%1],16;" :: "r"(dbh), "l"(gB_hi + kk));
        asm volatile("cp.async.cg.shared.global [%0],[%1],16;" :: "r"(dbl), "l"(gB_lo + kk));
    };

    auto compute = [&](int st) {
        const __nv_bfloat16* Ah = sA + (st * 2 + 0) * TSZ;
        const __nv_bfloat16* Al = sA + (st * 2 + 1) * TSZ;
        const __nv_bfloat16* Bh = sB + (st * 2 + 0) * TSZ;
        const __nv_bfloat16* Bl = sB + (st * 2 + 1) * TSZ;
        #pragma unroll
        for (int k16 = 0; k16 < 32; k16 += 16) {
            unsigned ahi[2][4], alo[2][4], bhi[2][2], blo[2][2];
            #pragma unroll
            for (int mt = 0; mt < 2; mt++) {
                int ra = wr * 32 + mt * 16 + g;
                const __nv_bfloat16* p = &Ah[ra * AST + k16 + tq * 2];
                ahi[mt][0] = *(const unsigned*)p;
                ahi[mt][1] = *(const unsigned*)(p + 8 * AST);
                ahi[mt][2] = *(const unsigned*)(p + 8);
                ahi[mt][3] = *(const unsigned*)(p + 8 * AST + 8);
                const __nv_bfloat16* q = &Al[ra * AST + k16 + tq * 2];
                alo[mt][0] = *(const unsigned*)q;
                alo[mt][1] = *(const unsigned*)(q + 8 * AST);
                alo[mt][2] = *(const unsigned*)(q + 8);
                alo[mt][3] = *(const unsigned*)(q + 8 * AST + 8);
            }
            #pragma unroll
            for (int nt = 0; nt < 2; nt++) {
                int cb = wc * 16 + nt * 8 + g;
                const __nv_bfloat16* p = &Bh[cb * AST + k16 + tq * 2];
                bhi[nt][0] = *(const unsigned*)p;
                bhi[nt][1] = *(const unsigned*)(p + 8);
                const __nv_bfloat16* q = &Bl[cb * AST + k16 + tq * 2];
                blo[nt][0] = *(const unsigned*)q;
                blo[nt][1] = *(const unsigned*)(q + 8);
            }
            #pragma unroll
            for (int mt = 0; mt < 2; mt++)
                #pragma unroll
                for (int nt = 0; nt < 2; nt++) {
                    mma16816(acc[mt][nt], ahi[mt], bhi[nt]);
                    mma16816(acc[mt][nt], ahi[mt], blo[nt]);
                    mma16816(acc[mt][nt], alo[mt], bhi[nt]);
                }
        }
    };

    int nk = K / 32;                      // 8 or 16, always >= 2
    issue(0, 0);
    asm volatile("cp.async.commit_group;");
    issue(32, 1);
    asm volatile("cp.async.commit_group;");

    int st = 0;
    for (int kt = 0; kt < nk; kt++) {
        if (kt + 1 < nk) asm volatile("cp.async.wait_group 1;");
        else             asm volatile("cp.async.wait_group 0;");
        __syncthreads();                  // tile kt visible; stage (kt+2)%3 WAR-safe
        if (kt + 2 < nk) {
            int st2 = st + 2; if (st2 >= 3) st2 -= 3;
            issue((kt + 2) * 32, st2);
            asm volatile("cp.async.commit_group;");
        }
        compute(st);
        if (++st == 3) st = 0;
    }

    #pragma unroll
    for (int mt = 0; mt < 2; mt++) {
        int r0 = m0 + wr * 32 + mt * 16 + g;
        #pragma unroll
        for (int nt = 0; nt < 2; nt++) {
            int c0 = n0 + wc * 16 + nt * 8 + tq * 2;
            float2 b2 = *(const float2*)&bias[c0];
            float2 o0 = {acc[mt][nt][0] + b2.x, acc[mt][nt][1] + b2.y};
            float2 o1 = {acc[mt][nt][2] + b2.x, acc[mt][nt][3] + b2.y};
            *(float2*)&C[r0 * Nc + c0] = o0;
            *(float2*)&C[(r0 + 8) * Nc + c0] = o1;
        }
    }
}

__global__ void __launch_bounds__(256) gemm_bf16split(
    const __nv_bfloat16* __restrict__ Ahi, const __nv_bfloat16* __restrict__ Alo,
    const __nv_bfloat16* __restrict__ Bhi, const __nv_bfloat16* __restrict__ Blo,
    const float* __restrict__ bias, float* __restrict__ C, int Nc, int K) {
    extern __shared__ __nv_bfloat16 smem[];
    gemm_body(smem, Ahi, Alo, Bhi, Blo, bias, C, Nc, K, blockIdx.y * 64, blockIdx.x * 64);
}

__global__ void __launch_bounds__(256) gemm_dual(
    const __nv_bfloat16* __restrict__ A0hi, const __nv_bfloat16* __restrict__ A0lo,
    const __nv_bfloat16* __restrict__ B0hi, const __nv_bfloat16* __restrict__ B0lo,
    const float* __restrict__ bias0, float* __restrict__ C0, int K0,
    const __nv_bfloat16* __restrict__ A1hi, const __nv_bfloat16* __restrict__ A1lo,
    const __nv_bfloat16* __restrict__ B1hi, const __nv_bfloat16* __restrict__ B1lo,
    const float* __restrict__ bias1, float* __restrict__ C1, int K1, int Nc) {
    extern __shared__ __nv_bfloat16 smem[];
    if (blockIdx.z == 0)
        gemm_body(smem, A0hi, A0lo, B0hi, B0lo, bias0, C0, Nc, K0, blockIdx.y * 64, blockIdx.x * 64);
    else
        gemm_body(smem, A1hi, A1lo, B1hi, B1lo, bias1, C1, Nc, K1, blockIdx.y * 64, blockIdx.x * 64);
}

// ---------------- sparse softmax attention + aggregate (low-sync, MLP-unrolled) -------
__global__ void attn_agg2(const float* __restrict__ eT0, const float* __restrict__ eT1,
                          const float* __restrict__ msgcat,
                          const float* __restrict__ ac0_, const float* __restrict__ an0_,
                          const float* __restrict__ ac1_, const float* __restrict__ an1_,
                          const float* __restrict__ ba0, const float* __restrict__ ba1,
                          __nv_bfloat16* __restrict__ ahi, __nv_bfloat16* __restrict__ alo) {
    __shared__ int   jl[512];
    __shared__ float wl[512];
    __shared__ float sv[512 * 4];
    __shared__ int   cnts[64];
    __shared__ int   offs[64];
    __shared__ int   sE;
    __shared__ float wred[8 * 4];
    __shared__ float hred[4];

    int t = blockIdx.y;
    const float* eT   = t ? eT1 : eT0;
    const float* acur = t ? ac1_ : ac0_;
    const float* anb  = t ? an1_ : an0_;
    const float* ba   = t ? ba1 : ba0;
    const float* msg  = msgcat + t * 256;

    int i = blockIdx.x;
    int tid = threadIdx.x;
    int lane = tid & 31, wid = tid >> 5;
    int oidx = i * 512 + t * 256 + tid;

    // 1) read 8 candidate edges; per-(q,warp) counts via ballot
    float v[8];
    unsigned m[8];
    bool f[8];
    const float* row = eT + (long)i * NN;
    #pragma unroll
    for (int q = 0; q < 8; q++) {
        float xv = row[q * 256 + tid];
        v[q] = xv;
        f[q] = (xv >= 0.f);
        m[q] = __ballot_sync(0xffffffffu, f[q]);
        if (lane == 0) cnts[q * 8 + wid] = __popc(m[q]);
    }
    __syncthreads();

    // 2) warp-0 shuffle scan of 64 counts (j-ascending order -> deterministic)
    if (wid == 0) {
        int c0 = cnts[lane], c1 = cnts[lane + 32];
        int s0 = c0, s1 = c1;
        #pragma unroll
        for (int o = 1; o < 32; o <<= 1) {
            int u0 = __shfl_up_sync(0xffffffffu, s0, o); if (lane >= o) s0 += u0;
            int u1 = __shfl_up_sync(0xffffffffu, s1, o); if (lane >= o) s1 += u1;
        }
        int tot0 = __shfl_sync(0xffffffffu, s0, 31);
        offs[lane] = s0 - c0;
        offs[lane + 32] = tot0 + s1 - c1;
        if (lane == 31) sE = tot0 + s1;
    }
    __syncthreads();

    int E = sE;
    if (E == 0) {
        __nv_bfloat16 z = __float2bfloat16(0.f);
        ahi[oidx] = z;
        alo[oidx] = z;
        return;
    }
    if (E > 512) E = 512;

    // 3) compacted write
    unsigned lt = (1u << lane) - 1u;
    #pragma unroll
    for (int q = 0; q < 8; q++) {
        if (f[q]) {
            int pos = offs[q * 8 + wid] + __popc(m[q] & lt);
            if (pos < 512) { jl[pos] = q * 256 + tid; wl[pos] = v[q]; }
        }
    }
    __syncthreads();

    // 4) scores + thread-local max
    float ac[4], bah[4];
    #pragma unroll
    for (int h = 0; h < 4; h++) { ac[h] = acur[i * 4 + h]; bah[h] = ba[h]; }

    float mx[4] = {-INFINITY, -INFINITY, -INFINITY, -INFINITY};
    for (int e = tid; e < E; e += 256) {
        int j = jl[e]; float w = wl[e];
        float4 a4 = *(const float4*)&anb[j * 4];
        float an_[4] = {a4.x, a4.y, a4.z, a4.w};
        #pragma unroll
        for (int h = 0; h < 4; h++) {
            float s = an_[h] + ac[h] + bah[h];
            s = s > 0.f ? s : 0.2f * s;
            s *= w;
            sv[e * 4 + h] = s;
            mx[h] = fmaxf(mx[h], s);
        }
    }
    #pragma unroll
    for (int h = 0; h < 4; h++)
        #pragma unroll
        for (int o = 16; o > 0; o >>= 1)
            mx[h] = fmaxf(mx[h], __shfl_xor_sync(0xffffffffu, mx[h], o));
    if (lane == 0)
        #pragma unroll
        for (int h = 0; h < 4; h++) wred[wid * 4 + h] = mx[h];
    __syncthreads();
    if (tid < 4) {
        float mm = wred[tid];
        #pragma unroll
        for (int w2 = 1; w2 < 8; w2++) mm = fmaxf(mm, wred[w2 * 4 + tid]);
        hred[tid] = mm;
    }
    __syncthreads();
    float hm[4] = {hred[0], hred[1], hred[2], hred[3]};

    // 5) exp + thread-local sum
    float sm[4] = {0.f, 0.f, 0.f, 0.f};
    for (int e = tid; e < E; e += 256) {
        #pragma unroll
        for (int h = 0; h < 4; h++) {
            float u = expf(sv[e * 4 + h] - hm[h]);
            sv[e * 4 + h] = u;
            sm[h] += u;
        }
    }
    #pragma unroll
    for (int h = 0; h < 4; h++)
        #pragma unroll
        for (int o = 16; o > 0; o >>= 1)
            sm[h] += __shfl_xor_sync(0xffffffffu, sm[h], o);
    if (lane == 0)
        #pragma unroll
        for (int h = 0; h < 4; h++) wred[wid * 4 + h] = sm[h];
    __syncthreads();
    if (tid < 4) {
        float ss = wred[tid];
        #pragma unroll
        for (int w2 = 1; w2 < 8; w2++) ss += wred[w2 * 4 + tid];
        hred[tid] = ss;
    }
    __syncthreads();

    // 6) aggregate, 4x unrolled for MLP; normalization folded in
    int d = tid, h = d >> 6;
    float acc = 0.f;
    int e = 0;
    for (; e + 4 <= E; e += 4) {
        int j0 = jl[e], j1 = jl[e + 1], j2 = jl[e + 2], j3 = jl[e + 3];
        float s0 = sv[(e) * 4 + h], s1 = sv[(e + 1) * 4 + h];
        float s2 = sv[(e + 2) * 4 + h], s3 = sv[(e + 3) * 4 + h];
        float m0_ = msg[j0 * 512 + d];
        float m1_ = msg[j1 * 512 + d];
        float m2_ = msg[j2 * 512 + d];
        float m3_ = msg[j3 * 512 + d];
        acc += s0 * m0_ + s1 * m1_ + s2 * m2_ + s3 * m3_;
    }
    for (; e < E; e++) acc += sv[e * 4 + h] * msg[jl[e] * 512 + d];
    acc *= (1.f / hred[h]);

    __nv_bfloat16 hb = __float2bfloat16(acc);
    ahi[oidx] = hb;
    alo[oidx] = __float2bfloat16(acc - __bfloat162float(hb));
}

// ---------------- GRU gates + LayerNorm ----------------
__global__ void gru_ln(const float* __restrict__ gi_, const float* __restrict__ gh_,
                       const float* __restrict__ x, const float* __restrict__ g,
                       const float* __restrict__ b, float* __restrict__ out) {
    int i = blockIdx.x, d = threadIdx.x;
    const float* gi = gi_ + i * 768;
    const float* gh = gh_ + i * 768;
    float r = 1.f / (1.f + expf(-(gi[d] + gh[d])));
    float z = 1.f / (1.f + expf(-(gi[256 + d] + gh[256 + d])));
    float n = tanhf(gi[512 + d] + r * gh[512 + d]);
    float hv = (1.f - z) * n + z * x[i * 256 + d];

    __shared__ float ssum[8], ssq[8];
    __shared__ float mu_s, rs_s;
    float s = hv, q = hv * hv;
    #pragma unroll
    for (int off = 16; off > 0; off >>= 1) {
        s += __shfl_down_sync(0xffffffffu, s, off);
        q += __shfl_down_sync(0xffffffffu, q, off);
    }
    int lane = d & 31, wid = d >> 5;
    if (lane == 0) { ssum[wid] = s; ssq[wid] = q; }
    __syncthreads();
    if (d == 0) {
        float S = 0.f, Q = 0.f;
        for (int w2 = 0; w2 < 8; w2++) { S += ssum[w2]; Q += ssq[w2]; }
        float mu = S / 256.f;
        float var = Q / 256.f - mu * mu;
        mu_s = mu;
        rs_s = rsqrtf(var + 1e-5f);
    }
    __syncthreads();
    out[i * 256 + d] = (hv - mu_s) * rs_s * g[d] + b[d];
}

// ---------------- host orchestration (single stream, 5 launches) ----------------
extern "C" void kernel_launch(void* const* d_in, const int* in_sizes, int n_in,
                              void* d_out, int out_size) {
    const float* x    = (const float*)d_in[0];
    const float* adj0 = (const float*)d_in[1];
    const float* adj1 = (const float*)d_in[2];
    const float* w0   = (const float*)d_in[3];
    const float* w1   = (const float*)d_in[4];
    const float* Wm0  = (const float*)d_in[5];
    const float* bm0  = (const float*)d_in[6];
    const float* Wa0  = (const float*)d_in[7];
    const float* ba0  = (const float*)d_in[8];
    const float* Wm1  = (const float*)d_in[9];
    const float* bm1  = (const float*)d_in[10];
    const float* Wa1  = (const float*)d_in[11];
    const float* ba1  = (const float*)d_in[12];
    const float* wih  = (const float*)d_in[13];
    const float* whh  = (const float*)d_in[14];
    const float* bih  = (const float*)d_in[15];
    const float* bhh  = (const float*)d_in[16];
    const float* lng  = (const float*)d_in[17];
    const float* lnb  = (const float*)d_in[18];
    float* out = (float*)d_out;

    float *msg, *e0, *e1, *gi, *gh, *ac0, *an0, *ac1, *an1, *bm;
    cudaGetSymbolAddress((void**)&msg, g_msg);
    cudaGetSymbolAddress((void**)&e0,  g_e0);
    cudaGetSymbolAddress((void**)&e1,  g_e1);
    cudaGetSymbolAddress((void**)&gi,  g_gi);
    cudaGetSymbolAddress((void**)&gh,  g_gh);
    cudaGetSymbolAddress((void**)&ac0, g_ac0);
    cudaGetSymbolAddress((void**)&an0, g_an0);
    cudaGetSymbolAddress((void**)&ac1, g_ac1);
    cudaGetSymbolAddress((void**)&an1, g_an1);
    cudaGetSymbolAddress((void**)&bm,  g_bm);

    __nv_bfloat16 *xhi, *xlo, *ahi, *alo, *wmhi, *wmlo, *wihhi, *wihlo, *whhhi, *whhlo;
    cudaGetSymbolAddress((void**)&xhi,   g_xhi);
    cudaGetSymbolAddress((void**)&xlo,   g_xlo);
    cudaGetSymbolAddress((void**)&ahi,   g_ahi);
    cudaGetSymbolAddress((void**)&alo,   g_alo);
    cudaGetSymbolAddress((void**)&wmhi,  g_wmhi);
    cudaGetSymbolAddress((void**)&wmlo,  g_wmlo);
    cudaGetSymbolAddress((void**)&wihhi, g_wihhi);
    cudaGetSymbolAddress((void**)&wihlo, g_wihlo);
    cudaGetSymbolAddress((void**)&whhhi, g_whhhi);
    cudaGetSymbolAddress((void**)&whhlo, g_whhlo);

    cudaFuncSetAttribute(gemm_bf16split,
                         cudaFuncAttributeMaxDynamicSharedMemorySize, GEMM_SMEM);
    cudaFuncSetAttribute(gemm_dual,
                         cudaFuncAttributeMaxDynamicSharedMemorySize, GEMM_SMEM);

    // 1) transpose+mask, acoef, bf16 splits, bias concat
    phase1<<<P1_GRID, 256>>>(x, adj0, w0, adj1, w1, Wa0, Wa1, Wm0, Wm1, wih, whh,
                             bm0, bm1, e0, e1, ac0, an0, ac1, an1,
                             xhi, xlo, wmhi, wmlo, wihhi, wihlo, whhhi, whhlo, bm);

    // 2) merged msg GEMM: [2048,512] = x @ [Wm0;Wm1]^T   (64x64 tiles -> 256 blocks)
    gemm_bf16split<<<dim3(8, 32), 256, GEMM_SMEM>>>(xhi, xlo, wmhi, wmlo, bm, msg, 512, 256);

    // 3) attention + aggregate (emits agg directly as bf16 hi/lo)
    attn_agg2<<<dim3(NN, 2), 256>>>(e0, e1, msg, ac0, an0, ac1, an1, ba0, ba1, ahi, alo);

    // 4) gi and gh GEMMs fused, 64x64 tiles -> 768 blocks
    gemm_dual<<<dim3(12, 32, 2), 256, GEMM_SMEM>>>(
        ahi, alo, wihhi, wihlo, bih, gi, 512,
        xhi, xlo, whhhi, whhlo, bhh, gh, 256, 768);

    // 5) GRU gates + LayerNorm
    gru_ln<<<NN, 256>>>(gi, gh, x, lng, lnb, out);
}